// round 7
// baseline (speedup 1.0000x reference)
#include <cuda_runtime.h>
#include <cuda_bf16.h>
#include <math.h>

// Problem constants
#define BB 128
#define TT 256
#define DD 256
#define HH 256

#define NBLK 128        // 16 clusters x 8 CTAs
#define CLU  8

typedef unsigned long long ull;

// ---------------- packed f32x2 helpers (Blackwell FFMA2 via PTX) ----------------
__device__ __forceinline__ ull pack2(float lo, float hi) {
    ull r; asm("mov.b64 %0, {%1, %2};" : "=l"(r) : "f"(lo), "f"(hi)); return r;
}
__device__ __forceinline__ void unpack2(float& lo, float& hi, ull v) {
    asm("mov.b64 {%0, %1}, %2;" : "=f"(lo), "=f"(hi) : "l"(v));
}
__device__ __forceinline__ ull fma2(ull a, ull b, ull c) {
    ull d; asm("fma.rn.f32x2 %0, %1, %2, %3;" : "=l"(d) : "l"(a), "l"(b), "l"(c));
    return d;
}

// ---------------- device scratch ----------------
__device__ float g_pre1[TT * BB * HH];   // pre1[t][b][h] row-major
__device__ float g_h2rm[BB * HH];        // final forward h2, row-major (for fc)
__device__ float g_h1bk[BB * HH];
__device__ float g_h2bk[BB * HH];

// ---------------- PTX wrappers ----------------
__device__ __forceinline__ unsigned smem_u32(const void* p) {
    unsigned a;
    asm("{ .reg .u64 t; cvta.to.shared.u64 t, %1; cvt.u32.u64 %0, t; }"
        : "=r"(a) : "l"(p));
    return a;
}
__device__ __forceinline__ void mbar_init(unsigned a, unsigned cnt) {
    asm volatile("mbarrier.init.shared.b64 [%0], %1;" :: "r"(a), "r"(cnt) : "memory");
}
__device__ __forceinline__ void expect_tx(unsigned a, unsigned bytes) {
    asm volatile("mbarrier.arrive.expect_tx.shared.b64 _, [%0], %1;"
                 :: "r"(a), "r"(bytes) : "memory");
}
__device__ __forceinline__ void waitp(unsigned a, unsigned par) {
    asm volatile(
        "{\n\t.reg .pred P;\n"
        "W%=:\n\t"
        "mbarrier.try_wait.parity.acquire.cluster.shared::cta.b64 P, [%0], %1, 0x989680;\n\t"
        "@!P bra W%=;\n\t}"
        :: "r"(a), "r"(par) : "memory");
}
__device__ __forceinline__ void st_async1(unsigned raddr, float v, unsigned rmbar) {
    asm volatile("st.async.shared::cluster.mbarrier::complete_tx::bytes.b32 [%0], %1, [%2];"
                 :: "r"(raddr), "r"(__float_as_uint(v)), "r"(rmbar) : "memory");
}

// ---------------- generic 64x64 register-blocked fp32 GEMM tile (FFMA2) ----------------
__device__ __forceinline__ void gemm64_body(
    const float* __restrict__ A, long lda,
    const float* __restrict__ A2, int ksplit, long lda2,
    const float* __restrict__ W, long ldw, int wtrans,
    const float* __restrict__ bias,
    float* __restrict__ C, long ldc,
    int K, int row0, int col0, int act,
    float* sA, float* sW)
{
    const int tid = threadIdx.x;
    const int tx = tid & 15;
    const int ty = tid >> 4;
    ull accp[4][2];
#pragma unroll
    for (int i = 0; i < 4; i++) { accp[i][0] = 0ull; accp[i][1] = 0ull; }

#pragma unroll 1
    for (int k0 = 0; k0 < K; k0 += 64) {
        const float* Ak = A; long ldak = lda; int kb = k0;
        if (A2 != nullptr && k0 >= ksplit) { Ak = A2; ldak = lda2; kb = k0 - ksplit; }

        __syncthreads();
#pragma unroll
        for (int p = 0; p < 4; p++) {
            int i = p * 256 + tid;
            int rr = i >> 4;
            int k4 = i & 15;
            float4 v = *(const float4*)(Ak + (long)(row0 + rr) * ldak + kb + k4 * 4);
            *(float4*)(sA + rr * 72 + k4 * 4) = v;
        }
        if (!wtrans) {
#pragma unroll
            for (int p = 0; p < 16; p++) {
                int i = p * 256 + tid;
                int kk = i >> 6, cc = i & 63;
                sW[kk * 72 + cc] = W[(long)(k0 + kk) * ldw + col0 + cc];
            }
        } else {
#pragma unroll
            for (int p = 0; p < 16; p++) {
                int i = p * 256 + tid;
                int kk = i & 63, cc = i >> 6;
                sW[kk * 72 + cc] = W[(long)(col0 + cc) * ldw + k0 + kk];
            }
        }
        __syncthreads();

#pragma unroll
        for (int k = 0; k < 64; k++) {
            ulonglong2 wv = *(const ulonglong2*)(sW + k * 72 + tx * 4);
#pragma unroll
            for (int i = 0; i < 4; i++) {
                float a = sA[(ty * 4 + i) * 72 + k];
                ull ap = pack2(a, a);
                accp[i][0] = fma2(ap, wv.x, accp[i][0]);
                accp[i][1] = fma2(ap, wv.y, accp[i][1]);
            }
        }
    }

#pragma unroll
    for (int i = 0; i < 4; i++) {
        float v0, v1, v2, v3;
        unpack2(v0, v1, accp[i][0]);
        unpack2(v2, v3, accp[i][1]);
        float vv[4] = {v0, v1, v2, v3};
#pragma unroll
        for (int j = 0; j < 4; j++) {
            int rr = row0 + ty * 4 + i;
            int cc = col0 + tx * 4 + j;
            float v = vv[j] + bias[cc];
            if (act) v = tanhf(v);
            C[(long)rr * ldc + cc] = v;
        }
    }
}

// ---------------- K1: precompute pre1[t] = x_t @ Wih_f[0,t] + b_f[0,t] ----------------
__global__ __launch_bounds__(256) void k_pre(
    const float* __restrict__ x, const float* __restrict__ Wih_f,
    const float* __restrict__ b_f)
{
    __shared__ float sA[64 * 72];
    __shared__ float sW[64 * 72];
    int t = blockIdx.y;
    int tile = blockIdx.x;
    int row0 = (tile >> 2) * 64;
    int col0 = (tile & 3) * 64;
    gemm64_body(x + (long)t * DD, (long)TT * DD,
                nullptr, 1 << 30, 0,
                Wih_f + (long)t * DD * HH, HH, 0,
                b_f + (long)t * HH,
                g_pre1 + (long)t * BB * HH, HH,
                DD, row0, col0, /*act=*/0, sA, sW);
}

// ================= K2: DSMEM-exchange persistent sequential scan =================
// Cluster (8 CTAs) = one row-group (8 batch rows). CTA rank owns 32 cols.
// h tiles exchanged via st.async directly into all 8 peers' smem + mbarrier
// complete_tx (8KB/tile). Double-buffered; parity (t>>1)&1; phase safety by
// t-2 transitivity. EXIT DRAIN: wait final m2 barrier + cluster barrier so no
// CTA exits while peers' st.async into its smem are in flight.

// weight slice: w[j] = W[(32s+j)][col0+c] (coalesced across warp per j)
__device__ __forceinline__ void pf_w(float (&w)[32], const float* __restrict__ W,
                                     int s, int c, int col0) {
    const float* p = W + (long)(s * 32) * HH + col0 + c;
#pragma unroll
    for (int j = 0; j < 32; j++) w[j] = __ldg(p + (long)j * HH);
}

// packed dot over this thread's 32-k slice; tile layout hsT[k*8 + r]
__device__ __forceinline__ void dotT(const float* hsT, const float (&w)[32], int s,
                                     ull& a01, ull& a23, ull& a45, ull& a67) {
#pragma unroll
    for (int k = 0; k < 32; k++) {
        const ulonglong2* p = (const ulonglong2*)(hsT + (s * 32 + k) * 8);
        ulonglong2 v0 = p[0];
        ulonglong2 v1 = p[1];
        ull wp = pack2(w[k], w[k]);
        a01 = fma2(v0.x, wp, a01);
        a23 = fma2(v0.y, wp, a23);
        a45 = fma2(v1.x, wp, a45);
        a67 = fma2(v1.y, wp, a67);
    }
}

// split-K reduction; trailing sync makes immediate buffer reuse safe
__device__ __forceinline__ float reduceT(float* red, ull a01, ull a23, ull a45, ull a67,
                                         int s, int c) {
    float r[8];
    unpack2(r[0], r[1], a01);
    unpack2(r[2], r[3], a23);
    unpack2(r[4], r[5], a45);
    unpack2(r[6], r[7], a67);
#pragma unroll
    for (int q = 0; q < 8; q++) red[s * 256 + q * 32 + c] = r[q];
    __syncthreads();
    float v = 0.f;
#pragma unroll
    for (int q = 0; q < 8; q++) v += red[q * 256 + s * 32 + c];
    __syncthreads();
    return v;
}

__global__ __launch_bounds__(256, 1) __cluster_dims__(CLU, 1, 1)
void k_seq(const float* __restrict__ Wih_f, const float* __restrict__ Whh_f,
           const float* __restrict__ b_f)
{
    __shared__ float hs1[2][8 * HH];              // h1 tiles, double-buffered (16 KB)
    __shared__ float hs2[2][8 * HH];              // h2 tiles (16 KB)
    __shared__ float red[8 * 256];                // split-K scratch (8 KB, shared)
    __shared__ __align__(8) ull mb[4];            // m1[0], m1[1], m2[0], m2[1]

    const int tid = threadIdx.x;
    const int s = tid >> 5;
    const int c = tid & 31;
    const int grp = blockIdx.x >> 3;
    const int rank = blockIdx.x & 7;
    const int row_base = grp * 8;
    const int col0 = rank * 32;
    const int rm_off = (row_base + s) * HH + col0 + c;

    const unsigned u_hs1 = smem_u32(&hs1[0][0]);
    const unsigned u_hs2 = smem_u32(&hs2[0][0]);
    const unsigned u_mb  = smem_u32(&mb[0]);
    const unsigned slot  = ((unsigned)(col0 + c) * 8 + s) * 4;   // byte offset in a tile

    if (tid == 0) {
#pragma unroll
        for (int i = 0; i < 4; i++) mbar_init(u_mb + i * 8, 1);
    }
    for (int i = tid; i < 8 * HH; i += 256) { hs1[1][i] = 0.f; hs2[1][i] = 0.f; }
    __syncthreads();
    asm volatile("barrier.cluster.arrive.aligned;" ::: "memory");
    asm volatile("barrier.cluster.wait.aligned;" ::: "memory");

    // per-rank DSMEM address deltas (aperture arithmetic is linear in offset)
    unsigned delta[CLU];
#pragma unroll
    for (int r2 = 0; r2 < CLU; r2++) {
        unsigned m;
        asm("mapa.shared::cluster.u32 %0, %1, %2;" : "=r"(m) : "r"(u_mb), "r"(r2));
        delta[r2] = m - u_mb;
    }

    const float* Whh1 = Whh_f;
    const float* Wih2 = Wih_f + (long)TT * DD * HH;
    const float* Whh2 = Whh_f + (long)TT * HH * HH;
    const float* b2   = b_f + (long)TT * HH;

    float wH1[32], wI2[32], wH2[32];
    pf_w(wH1, Whh1, s, c, col0);
    pf_w(wH2, Whh2, s, c, col0);
    pf_w(wI2, Wih2, s, c, col0);
    float pre = __ldg(g_pre1 + rm_off);

#pragma unroll 1
    for (int t = 0; t < TT; t++) {
        const int buf = t & 1;
        const int prev = buf ^ 1;
        const int tn = (t < TT - 1) ? t + 1 : t;
        const unsigned par_prev = ((unsigned)(t - 1) >> 1) & 1;   // tile t-1 parity
        const unsigned par_cur  = ((unsigned)t >> 1) & 1;         // tile t parity
        const unsigned m1b = u_mb + buf * 8;
        const unsigned m1p = u_mb + prev * 8;
        const unsigned m2b = u_mb + 16 + buf * 8;
        const unsigned m2p = u_mb + 16 + prev * 8;

        // announce expected bytes for tile t (phase-safe: tile t-2 observed complete
        // last iteration; mbarrier tx accounting tolerates completes-before-expect)
        if (tid == 0) { expect_tx(m1b, 8192); expect_tx(m2b, 8192); }

        // ---- phase A: h1[t] = tanh(pre + h1[t-1] @ Whh1[t]) ----
        if (t > 0) waitp(m1p, par_prev);
        ull a01 = 0ull, a23 = 0ull, a45 = 0ull, a67 = 0ull;
        dotT(&hs1[prev][0], wH1, s, a01, a23, a45, a67);
        float dA = reduceT(red, a01, a23, a45, a67, s, c);
        float h1v = tanhf(pre + dA);
        {
            unsigned la = u_hs1 + (unsigned)buf * (8 * HH * 4) + slot;
#pragma unroll
            for (int r2 = 0; r2 < CLU; r2++)
                st_async1(la + delta[r2], h1v, m1b + delta[r2]);
        }
        pf_w(wH1, Whh1 + (long)tn * HH * HH, s, c, col0);   // reload, hidden

        // ---- phase B: h2[t] = tanh(b2 + h2[t-1]@Whh2[t] + h1[t]@Wih2[t]) ----
        if (t > 0) waitp(m2p, par_prev);
        a01 = 0ull; a23 = 0ull; a45 = 0ull; a67 = 0ull;
        dotT(&hs2[prev][0], wH2, s, a01, a23, a45, a67);
        float bias = __ldg(b2 + (long)t * HH + col0 + c);
        pre = __ldg(g_pre1 + (long)tn * BB * HH + rm_off);  // prefetch next pre
        pf_w(wH2, Whh2 + (long)tn * HH * HH, s, c, col0);   // reload, hidden

        waitp(m1b, par_cur);                                 // h1[t] tile complete
        dotT(&hs1[buf][0], wI2, s, a01, a23, a45, a67);
        float dB = reduceT(red, a01, a23, a45, a67, s, c);
        float h2v = tanhf(bias + dB);
        {
            unsigned la = u_hs2 + (unsigned)buf * (8 * HH * 4) + slot;
#pragma unroll
            for (int r2 = 0; r2 < CLU; r2++)
                st_async1(la + delta[r2], h2v, m2b + delta[r2]);
        }
        if (t == TT - 1) g_h2rm[rm_off] = h2v;               // final state, row-major
        pf_w(wI2, Wih2 + (long)tn * DD * HH, s, c, col0);    // reload, hidden
    }

    // ---- exit drain: all inbound st.async must land before any CTA exits ----
    waitp(u_mb + 16 + ((TT - 1) & 1) * 8, ((TT - 1) >> 1) & 1);  // final h2 tile
    __syncthreads();
    asm volatile("barrier.cluster.arrive.aligned;" ::: "memory");
    asm volatile("barrier.cluster.wait.aligned;" ::: "memory");
}

// ---------------- tail kernels: backward single step + fc head ----------------
__global__ __launch_bounds__(256) void k_tail_a(
    const float* __restrict__ x, const float* __restrict__ Wih_b,
    const float* __restrict__ b_b)
{
    __shared__ float sA[64 * 72];
    __shared__ float sW[64 * 72];
    int tile = blockIdx.x;
    int row0 = (tile >> 2) * 64, col0 = (tile & 3) * 64;
    gemm64_body(x + (long)(TT - 1) * DD, (long)TT * DD,
                nullptr, 1 << 30, 0,
                Wih_b + (long)(TT - 1) * DD * HH, HH, 0,
                b_b + (long)(TT - 1) * HH,
                g_h1bk, HH, DD, row0, col0, /*act=*/1, sA, sW);
}

__global__ __launch_bounds__(256) void k_tail_b(
    const float* __restrict__ Wih_b, const float* __restrict__ b_b)
{
    __shared__ float sA[64 * 72];
    __shared__ float sW[64 * 72];
    int tile = blockIdx.x;
    int row0 = (tile >> 2) * 64, col0 = (tile & 3) * 64;
    gemm64_body(g_h1bk, HH,
                nullptr, 1 << 30, 0,
                Wih_b + (long)(TT + TT - 1) * DD * HH, HH, 0,
                b_b + (long)(TT + TT - 1) * HH,
                g_h2bk, HH, HH, row0, col0, /*act=*/1, sA, sW);
}

__global__ __launch_bounds__(256) void k_tail_c(
    const float* __restrict__ fc_w, const float* __restrict__ fc_b,
    float* __restrict__ out)
{
    __shared__ float sA[64 * 72];
    __shared__ float sW[64 * 72];
    int tile = blockIdx.x;
    int row0 = (tile >> 2) * 64, col0 = (tile & 3) * 64;
    gemm64_body(g_h2rm, HH,
                g_h2bk, /*ksplit=*/HH, HH,
                fc_w, 2 * HH, /*wtrans=*/1,
                fc_b,
                out, HH, 2 * HH, row0, col0, /*act=*/0, sA, sW);
}

// ---------------- launcher ----------------
extern "C" void kernel_launch(void* const* d_in, const int* in_sizes, int n_in,
                              void* d_out, int out_size) {
    const float* x     = (const float*)d_in[0];
    const float* Wih_f = (const float*)d_in[1];
    const float* Whh_f = (const float*)d_in[2];
    const float* b_f   = (const float*)d_in[3];
    const float* Wih_b = (const float*)d_in[4];
    // d_in[5] = Whh_b: unused (backward output at t=T-1 starts from h0=0)
    const float* b_b   = (const float*)d_in[6];
    const float* fc_w  = (const float*)d_in[7];
    const float* fc_b  = (const float*)d_in[8];
    float* out = (float*)d_out;
    (void)in_sizes; (void)n_in; (void)out_size;

    k_pre<<<dim3(8, TT), 256>>>(x, Wih_f, b_f);
    k_seq<<<NBLK, 256>>>(Wih_f, Whh_f, b_f);
    k_tail_a<<<8, 256>>>(x, Wih_b, b_b);
    k_tail_b<<<8, 256>>>(Wih_b, b_b);
    k_tail_c<<<8, 256>>>(fc_w, fc_b, out);
}

// round 8
// speedup vs baseline: 2.0239x; 2.0239x over previous
#include <cuda_runtime.h>
#include <cuda_bf16.h>
#include <math.h>

// Problem constants
#define BB 128
#define TT 256
#define DD 256
#define HH 256

#define NBLK 128        // 16 groups x (4 layer-1 CTAs + 4 layer-2 CTAs)
#define NGRP 16

typedef unsigned long long ull;

// ---------------- packed f32x2 helpers (Blackwell FFMA2 via PTX) ----------------
__device__ __forceinline__ ull pack2(float lo, float hi) {
    ull r; asm("mov.b64 %0, {%1, %2};" : "=l"(r) : "f"(lo), "f"(hi)); return r;
}
__device__ __forceinline__ void unpack2(float& lo, float& hi, ull v) {
    asm("mov.b64 {%0, %1}, %2;" : "=f"(lo), "=f"(hi) : "l"(v));
}
__device__ __forceinline__ ull fma2(ull a, ull b, ull c) {
    ull d; asm("fma.rn.f32x2 %0, %1, %2, %3;" : "=l"(d) : "l"(a), "l"(b), "l"(c));
    return d;
}

// ---------------- device scratch ----------------
// h tiles stored in GROUP-TILE layout: [t or buf][grp][col*8 + r] (2048 floats/tile)
__device__ float g_pre1[TT * BB * HH];          // pre1[t][b][h] row-major (incl b1)
__device__ float g_h1all[(long)TT * NGRP * 2048];  // h1[t], non-destructive (33.5 MB)
__device__ float g_h2t[2][NGRP * 2048];         // h2 ring, depth 2
__device__ float g_h2rm[BB * HH];               // final forward h2, row-major
__device__ float g_h1bk[BB * HH];
__device__ float g_h2bk[BB * HH];
__device__ unsigned g_f1[NGRP * 32];            // per-group flags, 128B apart
__device__ unsigned g_f2[NGRP * 32];

// ---------------- reset kernel (per-replay determinism) ----------------
__global__ void k_reset() {
    unsigned i = blockIdx.x * blockDim.x + threadIdx.x;
    if (i < NGRP * 32) { g_f1[i] = 0u; g_f2[i] = 0u; }
}

// ---------------- release/acquire flag ops ----------------
__device__ __forceinline__ void signal(unsigned* p) {
    __syncthreads();   // all threads' h stores precede the release
    if (threadIdx.x == 0)
        asm volatile("red.release.gpu.add.u32 [%0], 1;" :: "l"(p) : "memory");
}
__device__ __forceinline__ void waitflag(unsigned* p, unsigned target) {
    if (threadIdx.x == 0) {
        unsigned v;
        do {
            asm volatile("ld.acquire.gpu.u32 %0, [%1];" : "=r"(v) : "l"(p) : "memory");
        } while (v < target);
    }
    __syncthreads();
}

// ---------------- generic 64x64 register-blocked fp32 GEMM tile (FFMA2) ----------------
__device__ __forceinline__ void gemm64_body(
    const float* __restrict__ A, long lda,
    const float* __restrict__ A2, int ksplit, long lda2,
    const float* __restrict__ W, long ldw, int wtrans,
    const float* __restrict__ bias,
    float* __restrict__ C, long ldc,
    int K, int row0, int col0, int act,
    float* sA, float* sW)
{
    const int tid = threadIdx.x;
    const int tx = tid & 15;
    const int ty = tid >> 4;
    ull accp[4][2];
#pragma unroll
    for (int i = 0; i < 4; i++) { accp[i][0] = 0ull; accp[i][1] = 0ull; }

#pragma unroll 1
    for (int k0 = 0; k0 < K; k0 += 64) {
        const float* Ak = A; long ldak = lda; int kb = k0;
        if (A2 != nullptr && k0 >= ksplit) { Ak = A2; ldak = lda2; kb = k0 - ksplit; }

        __syncthreads();
#pragma unroll
        for (int p = 0; p < 4; p++) {
            int i = p * 256 + tid;
            int rr = i >> 4;
            int k4 = i & 15;
            float4 v = *(const float4*)(Ak + (long)(row0 + rr) * ldak + kb + k4 * 4);
            *(float4*)(sA + rr * 72 + k4 * 4) = v;
        }
        if (!wtrans) {
#pragma unroll
            for (int p = 0; p < 16; p++) {
                int i = p * 256 + tid;
                int kk = i >> 6, cc = i & 63;
                sW[kk * 72 + cc] = W[(long)(k0 + kk) * ldw + col0 + cc];
            }
        } else {
#pragma unroll
            for (int p = 0; p < 16; p++) {
                int i = p * 256 + tid;
                int kk = i & 63, cc = i >> 6;
                sW[kk * 72 + cc] = W[(long)(col0 + cc) * ldw + k0 + kk];
            }
        }
        __syncthreads();

#pragma unroll
        for (int k = 0; k < 64; k++) {
            ulonglong2 wv = *(const ulonglong2*)(sW + k * 72 + tx * 4);
#pragma unroll
            for (int i = 0; i < 4; i++) {
                float a = sA[(ty * 4 + i) * 72 + k];
                ull ap = pack2(a, a);
                accp[i][0] = fma2(ap, wv.x, accp[i][0]);
                accp[i][1] = fma2(ap, wv.y, accp[i][1]);
            }
        }
    }

#pragma unroll
    for (int i = 0; i < 4; i++) {
        float v0, v1, v2, v3;
        unpack2(v0, v1, accp[i][0]);
        unpack2(v2, v3, accp[i][1]);
        float vv[4] = {v0, v1, v2, v3};
#pragma unroll
        for (int j = 0; j < 4; j++) {
            int rr = row0 + ty * 4 + i;
            int cc = col0 + tx * 4 + j;
            float v = vv[j] + bias[cc];
            if (act) v = tanhf(v);
            C[(long)rr * ldc + cc] = v;
        }
    }
}

// ---------------- K1: precompute pre1[t] = x_t @ Wih_f[0,t] + b_f[0,t] ----------------
__global__ __launch_bounds__(256) void k_pre(
    const float* __restrict__ x, const float* __restrict__ Wih_f,
    const float* __restrict__ b_f)
{
    __shared__ float sA[64 * 72];
    __shared__ float sW[64 * 72];
    int t = blockIdx.y;
    int tile = blockIdx.x;
    int row0 = (tile >> 2) * 64;
    int col0 = (tile & 3) * 64;
    gemm64_body(x + (long)t * DD, (long)TT * DD,
                nullptr, 1 << 30, 0,
                Wih_f + (long)t * DD * HH, HH, 0,
                b_f + (long)t * HH,
                g_pre1 + (long)t * BB * HH, HH,
                DD, row0, col0, /*act=*/0, sA, sW);
}

// ================= K2: layer-split wavefront persistent scan =================
// Group g (8 batch rows): CTAs sub 0-3 = layer 1 (64 cols each), sub 4-7 =
// layer 2. Layer 2 lags layer 1 by one timestep; both recurrence chains run
// concurrently, so only ONE L2-exchange round-trip sits on each chain.
// h1[t] stored non-destructively per t (no WAR); h2 ring depth 2 (safe: a
// peer writes h2[t] only after observing all f2 signals for t-1, which
// happen after everyone staged h2[t-2]).

// thread (s = tid>>6 in 0..3 : 64-wide k-slice, c = tid&63 : column)

// weight slice: w[j] = W[(64s+j)][col0+c] (coalesced across warp per j)
__device__ __forceinline__ void pf64(float (&w)[64], const float* __restrict__ W,
                                     int s, int c, int col0) {
    const float* p = W + (long)(s * 64) * HH + col0 + c;
#pragma unroll
    for (int j = 0; j < 64; j++) w[j] = __ldg(p + (long)j * HH);
}

// stage a 2048-float group tile (layout matches smem exactly) — fully coalesced
__device__ __forceinline__ void stage(float* dst, const float* __restrict__ src,
                                      int tid) {
    float4 v0 = __ldcg((const float4*)(src + tid * 8));
    float4 v1 = __ldcg((const float4*)(src + tid * 8 + 4));
    *(float4*)(dst + tid * 8)     = v0;
    *(float4*)(dst + tid * 8 + 4) = v1;
}

// packed dot over this thread's 64-k slice; tile layout hsT[k*8 + r]
__device__ __forceinline__ void dot64(const float* hsT, const float (&w)[64], int s,
                                      ull& a01, ull& a23, ull& a45, ull& a67) {
#pragma unroll
    for (int k = 0; k < 64; k++) {
        const ulonglong2* p = (const ulonglong2*)(hsT + (s * 64 + k) * 8);
        ulonglong2 v0 = p[0];
        ulonglong2 v1 = p[1];
        ull wp = pack2(w[k], w[k]);
        a01 = fma2(v0.x, wp, a01);
        a23 = fma2(v0.y, wp, a23);
        a45 = fma2(v1.x, wp, a45);
        a67 = fma2(v1.y, wp, a67);
    }
}

// split-K reduce: thread (s,c) gets output rows s and s+4 of column c
__device__ __forceinline__ void reduce2(float* red, ull a01, ull a23, ull a45, ull a67,
                                        int s, int c, float& o0, float& o4) {
    float r[8];
    unpack2(r[0], r[1], a01);
    unpack2(r[2], r[3], a23);
    unpack2(r[4], r[5], a45);
    unpack2(r[6], r[7], a67);
#pragma unroll
    for (int q = 0; q < 8; q++) red[(s * 8 + q) * 64 + c] = r[q];
    __syncthreads();
    o0 = 0.f; o4 = 0.f;
#pragma unroll
    for (int q = 0; q < 4; q++) {
        o0 += red[(q * 8 + s) * 64 + c];
        o4 += red[(q * 8 + s + 4) * 64 + c];
    }
}

__global__ __launch_bounds__(256, 1)
void k_seq(const float* __restrict__ Wih_f, const float* __restrict__ Whh_f,
           const float* __restrict__ b_f)
{
    __shared__ float hsA[2048];       // 8 KB
    __shared__ float hsB[2048];       // 8 KB (layer 2 only)
    __shared__ float red[2048];       // 8 KB
    const int tid = threadIdx.x;
    const int s = tid >> 6;
    const int c = tid & 63;
    const int grp = blockIdx.x >> 3;
    const int sub = blockIdx.x & 7;
    const int layer = sub >> 2;
    const int col0 = (sub & 3) * 64;
    const int row_base = grp * 8;
    const int tidx = (col0 + c) * 8 + s;                 // tile slot (row s)
    const int rm = (row_base + s) * HH + col0 + c;       // row-major (pre1)
    const long gtile = (long)grp * 2048;
    unsigned* f1 = &g_f1[grp * 32];
    unsigned* f2 = &g_f2[grp * 32];

    const float* Whh1 = Whh_f;
    const float* Wih2 = Wih_f + (long)TT * DD * HH;
    const float* Whh2 = Whh_f + (long)TT * HH * HH;
    const float* b2   = b_f + (long)TT * HH;

    if (layer == 0) {
        // ---------------- layer 1 producer ----------------
        float w[64];
        pf64(w, Whh1, s, c, col0);
        float preA = __ldg(g_pre1 + rm);
        float preB = __ldg(g_pre1 + rm + 4 * HH);
        for (int i = tid; i < 2048; i += 256) hsA[i] = 0.f;   // h1[-1] = 0
        __syncthreads();

#pragma unroll 1
        for (int t = 0; t < TT; t++) {
            const int tn = (t < TT - 1) ? t + 1 : t;
            ull a01 = 0ull, a23 = 0ull, a45 = 0ull, a67 = 0ull;
            dot64(hsA, w, s, a01, a23, a45, a67);
            float r0, r4;
            reduce2(red, a01, a23, a45, a67, s, c, r0, r4);
            float hA = tanhf(preA + r0);
            float hB = tanhf(preB + r4);
            float* dst = g_h1all + ((long)t * NGRP) * 2048 + gtile;
            __stcg(dst + tidx, hA);
            __stcg(dst + tidx + 4, hB);
            signal(f1);
            pf64(w, Whh1 + (long)tn * HH * HH, s, c, col0);        // hidden reload
            preA = __ldg(g_pre1 + (long)tn * BB * HH + rm);
            preB = __ldg(g_pre1 + (long)tn * BB * HH + rm + 4 * HH);
            if (t < TT - 1) {
                waitflag(f1, 4u * (unsigned)(t + 1));
                stage(hsA, g_h1all + ((long)t * NGRP) * 2048 + gtile, tid);
                __syncthreads();
            }
        }
    } else {
        // ---------------- layer 2 consumer (lags by one step) ----------------
        float wI[64], wH[64];
        pf64(wI, Wih2, s, c, col0);
        pf64(wH, Whh2, s, c, col0);
        float bias = __ldg(b2 + col0 + c);
        for (int i = tid; i < 2048; i += 256) hsB[i] = 0.f;   // h2[-1] = 0
        __syncthreads();

#pragma unroll 1
        for (int t = 0; t < TT; t++) {
            const int tn = (t < TT - 1) ? t + 1 : t;

            // h1[t] (layer 1 runs ahead; wait usually satisfied)
            waitflag(f1, 4u * (unsigned)(t + 1));
            stage(hsA, g_h1all + ((long)t * NGRP) * 2048 + gtile, tid);
            __syncthreads();
            ull a01 = 0ull, a23 = 0ull, a45 = 0ull, a67 = 0ull;
            dot64(hsA, wI, s, a01, a23, a45, a67);        // h1[t] @ Wih2[t]
            pf64(wI, Wih2 + (long)tn * DD * HH, s, c, col0);

            // h2[t-1] — the actual recurrence chain
            if (t > 0) {
                waitflag(f2, 4u * (unsigned)t);
                stage(hsB, g_h2t[(t - 1) & 1] + gtile, tid);
                __syncthreads();
            }
            dot64(hsB, wH, s, a01, a23, a45, a67);        // + h2[t-1] @ Whh2[t]
            float r0, r4;
            reduce2(red, a01, a23, a45, a67, s, c, r0, r4);
            float hA = tanhf(bias + r0);
            float hB = tanhf(bias + r4);
            float* dst = g_h2t[t & 1] + gtile;
            __stcg(dst + tidx, hA);
            __stcg(dst + tidx + 4, hB);
            if (t == TT - 1) {                            // final state, row-major
                g_h2rm[rm] = hA;
                g_h2rm[rm + 4 * HH] = hB;
            }
            signal(f2);
            pf64(wH, Whh2 + (long)tn * HH * HH, s, c, col0);
            bias = __ldg(b2 + (long)tn * HH + col0 + c);
        }
    }
}

// ---------------- tail kernels: backward single step + fc head ----------------
__global__ __launch_bounds__(256) void k_tail_a(
    const float* __restrict__ x, const float* __restrict__ Wih_b,
    const float* __restrict__ b_b)
{
    __shared__ float sA[64 * 72];
    __shared__ float sW[64 * 72];
    int tile = blockIdx.x;
    int row0 = (tile >> 2) * 64, col0 = (tile & 3) * 64;
    gemm64_body(x + (long)(TT - 1) * DD, (long)TT * DD,
                nullptr, 1 << 30, 0,
                Wih_b + (long)(TT - 1) * DD * HH, HH, 0,
                b_b + (long)(TT - 1) * HH,
                g_h1bk, HH, DD, row0, col0, /*act=*/1, sA, sW);
}

__global__ __launch_bounds__(256) void k_tail_b(
    const float* __restrict__ Wih_b, const float* __restrict__ b_b)
{
    __shared__ float sA[64 * 72];
    __shared__ float sW[64 * 72];
    int tile = blockIdx.x;
    int row0 = (tile >> 2) * 64, col0 = (tile & 3) * 64;
    gemm64_body(g_h1bk, HH,
                nullptr, 1 << 30, 0,
                Wih_b + (long)(TT + TT - 1) * DD * HH, HH, 0,
                b_b + (long)(TT + TT - 1) * HH,
                g_h2bk, HH, HH, row0, col0, /*act=*/1, sA, sW);
}

__global__ __launch_bounds__(256) void k_tail_c(
    const float* __restrict__ fc_w, const float* __restrict__ fc_b,
    float* __restrict__ out)
{
    __shared__ float sA[64 * 72];
    __shared__ float sW[64 * 72];
    int tile = blockIdx.x;
    int row0 = (tile >> 2) * 64, col0 = (tile & 3) * 64;
    gemm64_body(g_h2rm, HH,
                g_h2bk, /*ksplit=*/HH, HH,
                fc_w, 2 * HH, /*wtrans=*/1,
                fc_b,
                out, HH, 2 * HH, row0, col0, /*act=*/0, sA, sW);
}

// ---------------- launcher ----------------
extern "C" void kernel_launch(void* const* d_in, const int* in_sizes, int n_in,
                              void* d_out, int out_size) {
    const float* x     = (const float*)d_in[0];
    const float* Wih_f = (const float*)d_in[1];
    const float* Whh_f = (const float*)d_in[2];
    const float* b_f   = (const float*)d_in[3];
    const float* Wih_b = (const float*)d_in[4];
    // d_in[5] = Whh_b: unused (backward output at t=T-1 starts from h0=0)
    const float* b_b   = (const float*)d_in[6];
    const float* fc_w  = (const float*)d_in[7];
    const float* fc_b  = (const float*)d_in[8];
    float* out = (float*)d_out;
    (void)in_sizes; (void)n_in; (void)out_size;

    k_reset<<<2, 256>>>();
    k_pre<<<dim3(8, TT), 256>>>(x, Wih_f, b_f);
    k_seq<<<NBLK, 256>>>(Wih_f, Whh_f, b_f);
    k_tail_a<<<8, 256>>>(x, Wih_b, b_b);
    k_tail_b<<<8, 256>>>(Wih_b, b_b);
    k_tail_c<<<8, 256>>>(fc_w, fc_b, out);
}

// round 9
// speedup vs baseline: 2.1465x; 1.0606x over previous
#include <cuda_runtime.h>
#include <cuda_bf16.h>
#include <math.h>

// Problem constants
#define BB 128
#define TT 256
#define DD 256
#define HH 256

#define NBLK 128        // 16 groups x (4 layer-1 CTAs + 4 layer-2 CTAs)
#define NGRP 16

typedef unsigned long long ull;

// ---------------- packed f32x2 helpers (Blackwell FFMA2 via PTX) ----------------
__device__ __forceinline__ ull pack2(float lo, float hi) {
    ull r; asm("mov.b64 %0, {%1, %2};" : "=l"(r) : "f"(lo), "f"(hi)); return r;
}
__device__ __forceinline__ void unpack2(float& lo, float& hi, ull v) {
    asm("mov.b64 {%0, %1}, %2;" : "=f"(lo), "=f"(hi) : "l"(v));
}
__device__ __forceinline__ ull fma2(ull a, ull b, ull c) {
    ull d; asm("fma.rn.f32x2 %0, %1, %2, %3;" : "=l"(d) : "l"(a), "l"(b), "l"(c));
    return d;
}

// ---------------- device scratch ----------------
// h tiles stored in GROUP-TILE layout: [t or buf][grp][col*8 + r] (2048 floats/tile)
__device__ float g_pre1[TT * BB * HH];          // pre1[t][b][h] row-major (incl b1)
__device__ float g_h1all[(long)TT * NGRP * 2048];  // h1[t], non-destructive (33.5 MB)
__device__ float g_h2t[2][NGRP * 2048];         // h2 ring, depth 2
__device__ float g_h2rm[BB * HH];               // final forward h2, row-major
__device__ float g_h1bk[BB * HH];
__device__ float g_h2bk[BB * HH];
__device__ unsigned g_f1[NGRP * 32];            // per-group flags, 128B apart
__device__ unsigned g_f2[NGRP * 32];

// ---------------- reset kernel (per-replay determinism) ----------------
__global__ void k_reset() {
    unsigned i = blockIdx.x * blockDim.x + threadIdx.x;
    if (i < NGRP * 32) { g_f1[i] = 0u; g_f2[i] = 0u; }
}

// ---------------- release/acquire flag ops ----------------
__device__ __forceinline__ void signal(unsigned* p) {
    __syncthreads();   // all threads' h stores precede the release
    if (threadIdx.x == 0)
        asm volatile("red.release.gpu.add.u32 [%0], 1;" :: "l"(p) : "memory");
}
__device__ __forceinline__ void waitflag(unsigned* p, unsigned target) {
    if (threadIdx.x == 0) {
        unsigned v;
        do {
            asm volatile("ld.acquire.gpu.u32 %0, [%1];" : "=r"(v) : "l"(p) : "memory");
        } while (v < target);
    }
    __syncthreads();
}

// ---------------- generic 64x64 register-blocked fp32 GEMM tile (FFMA2) ----------------
__device__ __forceinline__ void gemm64_body(
    const float* __restrict__ A, long lda,
    const float* __restrict__ A2, int ksplit, long lda2,
    const float* __restrict__ W, long ldw, int wtrans,
    const float* __restrict__ bias,
    float* __restrict__ C, long ldc,
    int K, int row0, int col0, int act,
    float* sA, float* sW)
{
    const int tid = threadIdx.x;
    const int tx = tid & 15;
    const int ty = tid >> 4;
    ull accp[4][2];
#pragma unroll
    for (int i = 0; i < 4; i++) { accp[i][0] = 0ull; accp[i][1] = 0ull; }

#pragma unroll 1
    for (int k0 = 0; k0 < K; k0 += 64) {
        const float* Ak = A; long ldak = lda; int kb = k0;
        if (A2 != nullptr && k0 >= ksplit) { Ak = A2; ldak = lda2; kb = k0 - ksplit; }

        __syncthreads();
#pragma unroll
        for (int p = 0; p < 4; p++) {
            int i = p * 256 + tid;
            int rr = i >> 4;
            int k4 = i & 15;
            float4 v = *(const float4*)(Ak + (long)(row0 + rr) * ldak + kb + k4 * 4);
            *(float4*)(sA + rr * 72 + k4 * 4) = v;
        }
        if (!wtrans) {
#pragma unroll
            for (int p = 0; p < 16; p++) {
                int i = p * 256 + tid;
                int kk = i >> 6, cc = i & 63;
                sW[kk * 72 + cc] = W[(long)(k0 + kk) * ldw + col0 + cc];
            }
        } else {
#pragma unroll
            for (int p = 0; p < 16; p++) {
                int i = p * 256 + tid;
                int kk = i & 63, cc = i >> 6;
                sW[kk * 72 + cc] = W[(long)(col0 + cc) * ldw + k0 + kk];
            }
        }
        __syncthreads();

#pragma unroll
        for (int k = 0; k < 64; k++) {
            ulonglong2 wv = *(const ulonglong2*)(sW + k * 72 + tx * 4);
#pragma unroll
            for (int i = 0; i < 4; i++) {
                float a = sA[(ty * 4 + i) * 72 + k];
                ull ap = pack2(a, a);
                accp[i][0] = fma2(ap, wv.x, accp[i][0]);
                accp[i][1] = fma2(ap, wv.y, accp[i][1]);
            }
        }
    }

#pragma unroll
    for (int i = 0; i < 4; i++) {
        float v0, v1, v2, v3;
        unpack2(v0, v1, accp[i][0]);
        unpack2(v2, v3, accp[i][1]);
        float vv[4] = {v0, v1, v2, v3};
#pragma unroll
        for (int j = 0; j < 4; j++) {
            int rr = row0 + ty * 4 + i;
            int cc = col0 + tx * 4 + j;
            float v = vv[j] + bias[cc];
            if (act) v = tanhf(v);
            C[(long)rr * ldc + cc] = v;
        }
    }
}

// ---------------- K1: precompute pre1[t] = x_t @ Wih_f[0,t] + b_f[0,t] ----------------
__global__ __launch_bounds__(256) void k_pre(
    const float* __restrict__ x, const float* __restrict__ Wih_f,
    const float* __restrict__ b_f)
{
    __shared__ float sA[64 * 72];
    __shared__ float sW[64 * 72];
    int t = blockIdx.y;
    int tile = blockIdx.x;
    int row0 = (tile >> 2) * 64;
    int col0 = (tile & 3) * 64;
    gemm64_body(x + (long)t * DD, (long)TT * DD,
                nullptr, 1 << 30, 0,
                Wih_f + (long)t * DD * HH, HH, 0,
                b_f + (long)t * HH,
                g_pre1 + (long)t * BB * HH, HH,
                DD, row0, col0, /*act=*/0, sA, sW);
}

// ================= K2: layer-split wavefront persistent scan =================
// Group g (8 batch rows): CTAs sub 0-3 = layer 1 (64 cols each), sub 4-7 =
// layer 2, lagging one timestep. KEY CHANGE vs R8: all weight prefetches
// (pf64 = 512 LDG wavefronts/warp into the L1tex queue) are issued AFTER the
// step's last critical staging load, so they drain during the ~2K-cyc dot
// instead of queueing ahead of the next exchange's critical loads.

// weight slice: w[j] = W[(64s+j)][col0+c] (coalesced across warp per j)
__device__ __forceinline__ void pf64(float (&w)[64], const float* __restrict__ W,
                                     int s, int c, int col0) {
    const float* p = W + (long)(s * 64) * HH + col0 + c;
#pragma unroll
    for (int j = 0; j < 64; j++) w[j] = __ldg(p + (long)j * HH);
}

// stage a 2048-float group tile (layout matches smem exactly) — fully coalesced
__device__ __forceinline__ void stage(float* dst, const float* __restrict__ src,
                                      int tid) {
    float4 v0 = __ldcg((const float4*)(src + tid * 8));
    float4 v1 = __ldcg((const float4*)(src + tid * 8 + 4));
    *(float4*)(dst + tid * 8)     = v0;
    *(float4*)(dst + tid * 8 + 4) = v1;
}

// packed dot over this thread's 64-k slice; tile layout hsT[k*8 + r]
__device__ __forceinline__ void dot64(const float* hsT, const float (&w)[64], int s,
                                      ull& a01, ull& a23, ull& a45, ull& a67) {
#pragma unroll
    for (int k = 0; k < 64; k++) {
        const ulonglong2* p = (const ulonglong2*)(hsT + (s * 64 + k) * 8);
        ulonglong2 v0 = p[0];
        ulonglong2 v1 = p[1];
        ull wp = pack2(w[k], w[k]);
        a01 = fma2(v0.x, wp, a01);
        a23 = fma2(v0.y, wp, a23);
        a45 = fma2(v1.x, wp, a45);
        a67 = fma2(v1.y, wp, a67);
    }
}

// split-K reduce: thread (s,c) gets output rows s and s+4 of column c
__device__ __forceinline__ void reduce2(float* red, ull a01, ull a23, ull a45, ull a67,
                                        int s, int c, float& o0, float& o4) {
    float r[8];
    unpack2(r[0], r[1], a01);
    unpack2(r[2], r[3], a23);
    unpack2(r[4], r[5], a45);
    unpack2(r[6], r[7], a67);
#pragma unroll
    for (int q = 0; q < 8; q++) red[(s * 8 + q) * 64 + c] = r[q];
    __syncthreads();
    o0 = 0.f; o4 = 0.f;
#pragma unroll
    for (int q = 0; q < 4; q++) {
        o0 += red[(q * 8 + s) * 64 + c];
        o4 += red[(q * 8 + s + 4) * 64 + c];
    }
}

__global__ __launch_bounds__(256, 1)
void k_seq(const float* __restrict__ Wih_f, const float* __restrict__ Whh_f,
           const float* __restrict__ b_f)
{
    __shared__ float hsA[2048];       // 8 KB
    __shared__ float hsB[2048];       // 8 KB (layer 2 only)
    __shared__ float red[2048];       // 8 KB
    const int tid = threadIdx.x;
    const int s = tid >> 6;
    const int c = tid & 63;
    const int grp = blockIdx.x >> 3;
    const int sub = blockIdx.x & 7;
    const int layer = sub >> 2;
    const int col0 = (sub & 3) * 64;
    const int row_base = grp * 8;
    const int tidx = (col0 + c) * 8 + s;                 // tile slot (row s)
    const int rm = (row_base + s) * HH + col0 + c;       // row-major (pre1)
    const long gtile = (long)grp * 2048;
    unsigned* f1 = &g_f1[grp * 32];
    unsigned* f2 = &g_f2[grp * 32];

    const float* Whh1 = Whh_f;
    const float* Wih2 = Wih_f + (long)TT * DD * HH;
    const float* Whh2 = Whh_f + (long)TT * HH * HH;
    const float* b2   = b_f + (long)TT * HH;

    if (layer == 0) {
        // ---------------- layer 1 producer ----------------
        float w[64];
        pf64(w, Whh1, s, c, col0);
        float preA = __ldg(g_pre1 + rm);
        float preB = __ldg(g_pre1 + rm + 4 * HH);
        for (int i = tid; i < 2048; i += 256) hsA[i] = 0.f;   // h1[-1] = 0
        __syncthreads();

#pragma unroll 1
        for (int t = 0; t < TT; t++) {
            const int tn = (t < TT - 1) ? t + 1 : t;
            ull a01 = 0ull, a23 = 0ull, a45 = 0ull, a67 = 0ull;
            dot64(hsA, w, s, a01, a23, a45, a67);
            float r0, r4;
            reduce2(red, a01, a23, a45, a67, s, c, r0, r4);
            float hA = tanhf(preA + r0);
            float hB = tanhf(preB + r4);
            float* dst = g_h1all + ((long)t * NGRP) * 2048 + gtile;
            __stcg(dst + tidx, hA);
            __stcg(dst + tidx + 4, hB);
            signal(f1);
            if (t < TT - 1) {
                waitflag(f1, 4u * (unsigned)(t + 1));
                stage(hsA, g_h1all + ((long)t * NGRP) * 2048 + gtile, tid);
                __syncthreads();
            }
            // prefetch burst AFTER the critical stage loads (drains during dot)
            pf64(w, Whh1 + (long)tn * HH * HH, s, c, col0);
            preA = __ldg(g_pre1 + (long)tn * BB * HH + rm);
            preB = __ldg(g_pre1 + (long)tn * BB * HH + rm + 4 * HH);
        }
    } else {
        // ---------------- layer 2 consumer (lags by one step) ----------------
        float wI[64], wH[64];
        pf64(wI, Wih2, s, c, col0);
        pf64(wH, Whh2, s, c, col0);
        float bias = __ldg(b2 + col0 + c);
        for (int i = tid; i < 2048; i += 256) hsB[i] = 0.f;   // h2[-1] = 0
        __syncthreads();

#pragma unroll 1
        for (int t = 0; t < TT; t++) {
            const int tn = (t < TT - 1) ? t + 1 : t;

            // h1[t] (layer 1 runs ahead; wait usually satisfied)
            waitflag(f1, 4u * (unsigned)(t + 1));
            stage(hsA, g_h1all + ((long)t * NGRP) * 2048 + gtile, tid);
            __syncthreads();
            ull a01 = 0ull, a23 = 0ull, a45 = 0ull, a67 = 0ull;
            dot64(hsA, wI, s, a01, a23, a45, a67);        // h1[t] @ Wih2[t]

            // h2[t-1] — the actual recurrence chain
            if (t > 0) {
                waitflag(f2, 4u * (unsigned)t);
                stage(hsB, g_h2t[(t - 1) & 1] + gtile, tid);
                __syncthreads();
            }
            dot64(hsB, wH, s, a01, a23, a45, a67);        // + h2[t-1] @ Whh2[t]
            float r0, r4;
            reduce2(red, a01, a23, a45, a67, s, c, r0, r4);
            float hA = tanhf(bias + r0);
            float hB = tanhf(bias + r4);
            float* dst = g_h2t[t & 1] + gtile;
            __stcg(dst + tidx, hA);
            __stcg(dst + tidx + 4, hB);
            if (t == TT - 1) {                            // final state, row-major
                g_h2rm[rm] = hA;
                g_h2rm[rm + 4 * HH] = hB;
            }
            signal(f2);
            // prefetch bursts AFTER all critical staging of this step
            pf64(wI, Wih2 + (long)tn * DD * HH, s, c, col0);
            pf64(wH, Whh2 + (long)tn * HH * HH, s, c, col0);
            bias = __ldg(b2 + (long)tn * HH + col0 + c);
        }
    }
}

// ---------------- tail kernels: backward single step + fc head ----------------
__global__ __launch_bounds__(256) void k_tail_a(
    const float* __restrict__ x, const float* __restrict__ Wih_b,
    const float* __restrict__ b_b)
{
    __shared__ float sA[64 * 72];
    __shared__ float sW[64 * 72];
    int tile = blockIdx.x;
    int row0 = (tile >> 2) * 64, col0 = (tile & 3) * 64;
    gemm64_body(x + (long)(TT - 1) * DD, (long)TT * DD,
                nullptr, 1 << 30, 0,
                Wih_b + (long)(TT - 1) * DD * HH, HH, 0,
                b_b + (long)(TT - 1) * HH,
                g_h1bk, HH, DD, row0, col0, /*act=*/1, sA, sW);
}

__global__ __launch_bounds__(256) void k_tail_b(
    const float* __restrict__ Wih_b, const float* __restrict__ b_b)
{
    __shared__ float sA[64 * 72];
    __shared__ float sW[64 * 72];
    int tile = blockIdx.x;
    int row0 = (tile >> 2) * 64, col0 = (tile & 3) * 64;
    gemm64_body(g_h1bk, HH,
                nullptr, 1 << 30, 0,
                Wih_b + (long)(TT + TT - 1) * DD * HH, HH, 0,
                b_b + (long)(TT + TT - 1) * HH,
                g_h2bk, HH, HH, row0, col0, /*act=*/1, sA, sW);
}

__global__ __launch_bounds__(256) void k_tail_c(
    const float* __restrict__ fc_w, const float* __restrict__ fc_b,
    float* __restrict__ out)
{
    __shared__ float sA[64 * 72];
    __shared__ float sW[64 * 72];
    int tile = blockIdx.x;
    int row0 = (tile >> 2) * 64, col0 = (tile & 3) * 64;
    gemm64_body(g_h2rm, HH,
                g_h2bk, /*ksplit=*/HH, HH,
                fc_w, 2 * HH, /*wtrans=*/1,
                fc_b,
                out, HH, 2 * HH, row0, col0, /*act=*/0, sA, sW);
}

// ---------------- launcher ----------------
// NOTE: launch order puts k_seq at position 4 — the slot the profiler has
// captured every round — so the next ncu report shows the kernel that matters.
// Dependency-safe: k_tail_a reads only inputs; k_tail_b(5) needs k_tail_a(3);
// k_tail_c(6) needs k_seq(4) + k_tail_b(5).
extern "C" void kernel_launch(void* const* d_in, const int* in_sizes, int n_in,
                              void* d_out, int out_size) {
    const float* x     = (const float*)d_in[0];
    const float* Wih_f = (const float*)d_in[1];
    const float* Whh_f = (const float*)d_in[2];
    const float* b_f   = (const float*)d_in[3];
    const float* Wih_b = (const float*)d_in[4];
    // d_in[5] = Whh_b: unused (backward output at t=T-1 starts from h0=0)
    const float* b_b   = (const float*)d_in[6];
    const float* fc_w  = (const float*)d_in[7];
    const float* fc_b  = (const float*)d_in[8];
    float* out = (float*)d_out;
    (void)in_sizes; (void)n_in; (void)out_size;

    k_reset<<<2, 256>>>();
    k_pre<<<dim3(8, TT), 256>>>(x, Wih_f, b_f);
    k_tail_a<<<8, 256>>>(x, Wih_b, b_b);
    k_seq<<<NBLK, 256>>>(Wih_f, Whh_f, b_f);
    k_tail_b<<<8, 256>>>(Wih_b, b_b);
    k_tail_c<<<8, 256>>>(fc_w, fc_b, out);
}